// round 13
// baseline (speedup 1.0000x reference)
#include <cuda_runtime.h>
#include <cstdint>
#include <cstddef>

// Problem constants
#define BATCH   32
#define DMODEL  2560
#define DINNER  5120
#define NSTATE  16
#define DTRANK  160
#define XDBDIM  192          // DTRANK + 2*NSTATE

// Split-K configs
#define SPLIT_IN   4         // K=2560 -> 640 each     (grid 20*2*4 = 160)
#define SPLIT_XP   80        // K=5120 -> 64 each      (grid 80)
#define SPLIT_OUT  14        // K=5120 -> 10x384+4x320 (grid 10*14 = 140)

#define KCH    32            // k per pipeline chunk
#define KPAD   36            // padded smem row stride (floats; 144B)
#define NSTAGE 4
#define TROWS  256
#define GEMM_SMEM (NSTAGE * (TROWS + 32) * KPAD * 4)   // 165888 bytes

// -------- scratch (static device globals; no allocation) ----------
__device__ __align__(256) float g_x32[BATCH * DMODEL];            // rna-tf32 x
__device__ __align__(256) float g_part_in[(2 * SPLIT_IN) * DINNER * BATCH];
__device__ __align__(256) float g_conv[BATCH * DINNER];           // rna-tf32
__device__ __align__(256) float g_g[BATCH * DINNER];
__device__ __align__(256) float g_part_b[SPLIT_XP * XDBDIM * BATCH];
__device__ __align__(256) float g_red[8 * XDBDIM * BATCH];
__device__ __align__(256) float g_z[BATCH * DINNER];              // rna-tf32
__device__ __align__(256) float g_part_c[SPLIT_OUT * DMODEL * BATCH];

// -------- helpers ----------
__device__ __forceinline__ uint32_t smem_u32(const void* p) {
    uint32_t r;
    asm("{.reg .u64 t; cvta.to.shared.u64 t, %1; cvt.u32.u64 %0, t;}"
        : "=r"(r) : "l"(p));
    return r;
}
__device__ __forceinline__ void cp_async16(uint32_t dst, const void* src) {
    asm volatile("cp.async.cg.shared.global [%0], [%1], 16;\n" ::"r"(dst), "l"(src));
}
__device__ __forceinline__ void cp_commit() {
    asm volatile("cp.async.commit_group;\n");
}
template <int N>
__device__ __forceinline__ void cp_wait() {
    asm volatile("cp.async.wait_group %0;\n" ::"n"(N));
}
__device__ __forceinline__ float silu_f(float v) {
    return v / (1.f + __expf(-v));
}
__device__ __forceinline__ float rn_tf32(float v) {
    uint32_t u;
    asm("cvt.rna.tf32.f32 %0, %1;" : "=r"(u) : "f"(v));
    return __uint_as_float(u);
}
__device__ __forceinline__ uint32_t rn_tf32_r(uint32_t v) {
    uint32_t u;
    asm("cvt.rna.tf32.f32 %0, %1;" : "=r"(u) : "f"(__uint_as_float(v)));
    return u;
}

// ldmatrix x4: four 8x8 b16 matrices (= four 8x4 fp32 blocks)
__device__ __forceinline__ void ldsm_x4(uint32_t& r0, uint32_t& r1,
                                        uint32_t& r2, uint32_t& r3,
                                        uint32_t addr) {
    asm volatile("ldmatrix.sync.aligned.m8n8.x4.shared.b16 {%0,%1,%2,%3}, [%4];"
                 : "=r"(r0), "=r"(r1), "=r"(r2), "=r"(r3) : "r"(addr));
}

// warp mma: D(16x8) += A(16x8,row) * B(8x8,col), tf32 inputs, f32 accum
__device__ __forceinline__ void mma_tf32(float* c, const uint32_t* a,
                                         const uint32_t* b) {
    asm volatile(
        "mma.sync.aligned.m16n8k8.row.col.f32.tf32.tf32.f32 "
        "{%0,%1,%2,%3}, {%4,%5,%6,%7}, {%8,%9}, {%0,%1,%2,%3};"
        : "+f"(c[0]), "+f"(c[1]), "+f"(c[2]), "+f"(c[3])
        : "r"(a[0]), "r"(a[1]), "r"(a[2]), "r"(a[3]), "r"(b[0]), "r"(b[1]));
}

// ===================================================================
// prep: round x to tf32-nearest (B operand of in-proj)
// ===================================================================
__global__ void __launch_bounds__(256) prep_x_kernel(const float* __restrict__ x) {
    int i = blockIdx.x * 256 + threadIdx.x;
    if (i < BATCH * DMODEL) g_x32[i] = rn_tf32(x[i]);
}

// ===================================================================
// Warp-MMA tf32 split-K GEMM: 256 threads, tile = 256 rows x 32 batch.
// Fragments via ldmatrix.x4.  4-stage cp.async pipeline, ONE
// __syncthreads per chunk.  A RNA-rounded post-ldmatrix; B pre-rounded.
// Writes partial to part[d*32 + b].  klen multiple of KCH.
// ===================================================================
__device__ __forceinline__ void gemm_mma(const float* __restrict__ W,
                                         const float* __restrict__ Bm,
                                         float* __restrict__ part,
                                         int M, int K, int k0, int klen, int row0) {
    extern __shared__ __align__(16) float dyn[];
    float* w_s = dyn;                             // [NSTAGE][TROWS*KPAD]
    float* x_s = dyn + NSTAGE * TROWS * KPAD;     // [NSTAGE][32*KPAD]

    const int tid = threadIdx.x;
    const int wid = tid >> 5;
    const int lane = tid & 31;
    const int gid = lane >> 2;    // 0..7
    const int t4 = lane & 3;      // 0..3
    const int lm = lane >> 3;     // ldmatrix matrix idx 0..3
    const int lr = lane & 7;      // ldmatrix row in matrix

    const int nch = klen / KCH;

    uint32_t ws_[NSTAGE], xs_[NSTAGE];
#pragma unroll
    for (int s = 0; s < NSTAGE; s++) {
        ws_[s] = smem_u32(w_s + s * TROWS * KPAD);
        xs_[s] = smem_u32(x_s + s * 32 * KPAD);
    }

    uint32_t a_off[2];
#pragma unroll
    for (int mt = 0; mt < 2; mt++)
        a_off[mt] = (uint32_t)(((wid * 32 + mt * 16 + (lm & 1) * 8 + lr) * KPAD
                                + (lm >> 1) * 4) * 4);
    uint32_t b_off[2];
#pragma unroll
    for (int p = 0; p < 2; p++)
        b_off[p] = (uint32_t)((((lm >> 1) * 8 + p * 16 + lr) * KPAD
                               + (lm & 1) * 4) * 4);

    auto fill = [&](int st, int c) {
        const int kc = k0 + c * KCH;
        uint32_t wd = ws_[st];
#pragma unroll
        for (int i = 0; i < 8; i++) {
            int p = tid + 256 * i;             // 0..2047
            int r = p >> 3, o = p & 7;
            int gr = row0 + r;
            gr = gr < M ? gr : M - 1;          // clamp (xp tail rows)
            cp_async16(wd + (uint32_t)(r * KPAD + o * 4) * 4,
                       W + (size_t)gr * K + kc + o * 4);
        }
        {
            int r = tid >> 3, o = tid & 7;     // 256 pieces exactly
            cp_async16(xs_[st] + (uint32_t)(r * KPAD + o * 4) * 4,
                       Bm + (size_t)r * K + kc + o * 4);
        }
        cp_commit();
    };

    fill(0, 0);
#pragma unroll
    for (int s = 1; s <= NSTAGE - 2; s++) {
        if (s < nch) fill(s % NSTAGE, s); else cp_commit();
    }

    float acc[2][4][4];
#pragma unroll
    for (int mt = 0; mt < 2; mt++)
#pragma unroll
        for (int nt = 0; nt < 4; nt++)
#pragma unroll
            for (int q = 0; q < 4; q++) acc[mt][nt][q] = 0.f;

    for (int c = 0; c < nch; c++) {
        cp_wait<NSTAGE - 2>();
        __syncthreads();
        const int st = c % NSTAGE;
        const uint32_t wsb = ws_[st];
        const uint32_t xsb = xs_[st];
#pragma unroll
        for (int kstep = 0; kstep < KCH / 8; kstep++) {
            const uint32_t kb = kstep * 32;   // 8 floats = 32 bytes
            uint32_t a[2][4], b[4][2];
#pragma unroll
            for (int mt = 0; mt < 2; mt++) {
                ldsm_x4(a[mt][0], a[mt][1], a[mt][2], a[mt][3],
                        wsb + a_off[mt] + kb);
                a[mt][0] = rn_tf32_r(a[mt][0]);
                a[mt][1] = rn_tf32_r(a[mt][1]);
                a[mt][2] = rn_tf32_r(a[mt][2]);
                a[mt][3] = rn_tf32_r(a[mt][3]);
            }
#pragma unroll
            for (int p = 0; p < 2; p++)
                ldsm_x4(b[p * 2][0], b[p * 2][1], b[p * 2 + 1][0],
                        b[p * 2 + 1][1], xsb + b_off[p] + kb);
#pragma unroll
            for (int mt = 0; mt < 2; mt++)
#pragma unroll
                for (int nt = 0; nt < 4; nt++)
                    mma_tf32(acc[mt][nt], a[mt], b[nt]);
        }
        if (c + NSTAGE - 1 < nch) fill((c + NSTAGE - 1) % NSTAGE, c + NSTAGE - 1);
        else cp_commit();
    }

    // store: D[m][n] -> part[d*32 + b]
#pragma unroll
    for (int mt = 0; mt < 2; mt++) {
        int d0 = row0 + wid * 32 + mt * 16 + gid;
        if (d0 < M) {
#pragma unroll
            for (int nt = 0; nt < 4; nt++) {
                int n = nt * 8 + 2 * t4;
                *(float2*)&part[(size_t)d0 * BATCH + n] =
                    make_float2(acc[mt][nt][0], acc[mt][nt][1]);
                if (d0 + 8 < M)
                    *(float2*)&part[(size_t)(d0 + 8) * BATCH + n] =
                        make_float2(acc[mt][nt][2], acc[mt][nt][3]);
            }
        }
    }
}

// ---- wrappers ----
__global__ void __launch_bounds__(256)
gemm_in_kernel(const float* __restrict__ Wssm, const float* __restrict__ Wmlp) {
    int sel = blockIdx.y, z = blockIdx.z;
    const float* W = sel ? Wmlp : Wssm;
    float* part = g_part_in + (size_t)(sel * SPLIT_IN + z) * DINNER * BATCH;
    gemm_mma(W, g_x32, part, DINNER, DMODEL, z * 640, 640, blockIdx.x * TROWS);
}

__global__ void __launch_bounds__(256)
gemm_xp_kernel(const float* __restrict__ Wxp) {
    int z = blockIdx.z;
    float* part = g_part_b + (size_t)z * XDBDIM * BATCH;
    gemm_mma(Wxp, g_conv, part, XDBDIM, DINNER, z * (DINNER / SPLIT_XP),
             DINNER / SPLIT_XP, 0);
}

__global__ void __launch_bounds__(256)
gemm_out_kernel(const float* __restrict__ Wout) {
    int z = blockIdx.z;
    int k0 = z < 10 ? z * 384 : 3840 + (z - 10) * 320;
    int klen = z < 10 ? 384 : 320;
    float* part = g_part_c + (size_t)z * DMODEL * BATCH;
    gemm_mma(Wout, g_z, part, DMODEL, DINNER, k0, klen, blockIdx.x * TROWS);
}

// ===================================================================
// Epilogue A: sum in_proj partials [z][d][b], conv + SiLU -> g_conv[b][d]
//             (tf32-rounded), gate SiLU -> g_g[b][d]
// grid (DINNER/128, 4): blockIdx.y selects 8 batches
// ===================================================================
__global__ void __launch_bounds__(128)
epi_a_kernel(const float* __restrict__ conv_states,
             const float* __restrict__ conv_w,
             const float* __restrict__ conv_b) {
    int d = blockIdx.x * 128 + threadIdx.x;
    int by = blockIdx.y;          // 0..3, batches [8*by, 8*by+8)
    float xs[8], res[8];
#pragma unroll
    for (int b = 0; b < 8; b++) { xs[b] = 0.f; res[b] = 0.f; }
#pragma unroll
    for (int z = 0; z < SPLIT_IN; z++) {
        const float4* p = (const float4*)(g_part_in +
            ((size_t)z * DINNER + d) * BATCH + by * 8);
        float4 v0 = p[0], v1 = p[1];
        xs[0] += v0.x; xs[1] += v0.y; xs[2] += v0.z; xs[3] += v0.w;
        xs[4] += v1.x; xs[5] += v1.y; xs[6] += v1.z; xs[7] += v1.w;
    }
#pragma unroll
    for (int z = SPLIT_IN; z < 2 * SPLIT_IN; z++) {
        const float4* p = (const float4*)(g_part_in +
            ((size_t)z * DINNER + d) * BATCH + by * 8);
        float4 v0 = p[0], v1 = p[1];
        res[0] += v0.x; res[1] += v0.y; res[2] += v0.z; res[3] += v0.w;
        res[4] += v1.x; res[5] += v1.y; res[6] += v1.z; res[7] += v1.w;
    }

    float cw0 = conv_w[d];
    float cw1 = conv_w[DINNER + d];
    float cw2 = conv_w[2 * DINNER + d];
    float cw3 = conv_w[3 * DINNER + d];
    float cb = conv_b[d];

#pragma unroll
    for (int bb = 0; bb < 8; bb++) {
        int b = by * 8 + bb;
        float conv = conv_states[(size_t)(1 * BATCH + b) * DINNER + d] * cw0
                   + conv_states[(size_t)(2 * BATCH + b) * DINNER + d] * cw1
                   + conv_states[(size_t)(3 * BATCH + b) * DINNER + d] * cw2
                   + xs[bb] * cw3 + cb;
        g_conv[(size_t)b * DINNER + d] = rn_tf32(silu_f(conv));
        g_g[(size_t)b * DINNER + d] = silu_f(res[bb]);
    }
}

// ===================================================================
// Epilogue B stage 1: 192 blocks; block (g = bx/24, tb = bx%24) sums
// z in [10g, 10g+10) for t = tb*256+tid  ->  g_red[g][t]
// (stage 2 fused into ssm_kernel)
// ===================================================================
__global__ void __launch_bounds__(256) epi_b1_kernel() {
    int g = blockIdx.x / 24;
    int t = (blockIdx.x % 24) * 256 + threadIdx.x;
    const float* base = g_part_b + (size_t)(g * 10) * XDBDIM * BATCH + t;
    float s = 0.f;
#pragma unroll
    for (int j = 0; j < 10; j++)
        s += base[(size_t)j * XDBDIM * BATCH];
    g_red[(size_t)g * XDBDIM * BATCH + t] = s;
}

// ===================================================================
// SSM kernel: sums the 8 g_red groups into smem xdb (fused epi_b2),
// then dt GEMV + softplus + state scan + gate -> g_z[b][d] (tf32)
// grid (DINNER/128, 8), block 128; blockIdx.y = 4-batch group
// ===================================================================
#define SSM_BB 4
__global__ void __launch_bounds__(128)
ssm_kernel(const float* __restrict__ W_dt, const float* __restrict__ dt_bias,
           const float* __restrict__ A_log, const float* __restrict__ Dv,
           const float* __restrict__ ssm_state) {
    __shared__ float xdb_s[XDBDIM * SSM_BB];
    const int by = blockIdx.y;
    for (int u = threadIdx.x; u < XDBDIM * SSM_BB; u += 128) {
        int r = u >> 2, bb = u & 3;
        size_t idx = (size_t)r * BATCH + by * SSM_BB + bb;
        float s = 0.f;
#pragma unroll
        for (int g = 0; g < 8; g++)
            s += g_red[(size_t)g * XDBDIM * BATCH + idx];
        xdb_s[u] = s;
    }
    __syncthreads();

    const int d = blockIdx.x * 128 + threadIdx.x;

    float accdt[SSM_BB];
#pragma unroll
    for (int bb = 0; bb < SSM_BB; bb++) accdt[bb] = 0.f;

    const float4* wd = (const float4*)(W_dt + (size_t)d * DTRANK);
#pragma unroll 10
    for (int r4 = 0; r4 < DTRANK / 4; r4++) {
        float4 w = wd[r4];
        float wa[4] = {w.x, w.y, w.z, w.w};
#pragma unroll
        for (int j = 0; j < 4; j++) {
            float4 xv = *(const float4*)&xdb_s[(r4 * 4 + j) * SSM_BB];
            accdt[0] += wa[j] * xv.x;
            accdt[1] += wa[j] * xv.y;
            accdt[2] += wa[j] * xv.z;
            accdt[3] += wa[j] * xv.w;
        }
    }

    float a[NSTATE];
    const float4* al = (const float4*)(A_log + (size_t)d * NSTATE);
#pragma unroll
    for (int n4 = 0; n4 < 4; n4++) {
        float4 v = al[n4];
        a[n4 * 4 + 0] = -__expf(v.x);
        a[n4 * 4 + 1] = -__expf(v.y);
        a[n4 * 4 + 2] = -__expf(v.z);
        a[n4 * 4 + 3] = -__expf(v.w);
    }
    float Dd = Dv[d];
    float bias = dt_bias[d];

#pragma unroll
    for (int bb = 0; bb < SSM_BB; bb++) {
        int b = by * SSM_BB + bb;
        float dtv = accdt[bb] + bias;
        float dt = dtv > 20.f ? dtv : log1pf(__expf(dtv));
        float c = g_conv[(size_t)b * DINNER + d];
        float gv = g_g[(size_t)b * DINNER + d];
        float y = Dd * c;
        const float4* s4 =
            (const float4*)(ssm_state + ((size_t)b * DINNER + d) * NSTATE);
#pragma unroll
        for (int n4 = 0; n4 < 4; n4++) {
            float4 s = s4[n4];
            float sa[4] = {s.x, s.y, s.z, s.w};
#pragma unroll
            for (int h = 0; h < 4; h++) {
                int n = n4 * 4 + h;
                float dA = __expf(dt * a[n]);
                float hv = sa[h] * dA + dt * xdb_s[(DTRANK + n) * SSM_BB + bb] * c;
                y += hv * xdb_s[(DTRANK + NSTATE + n) * SSM_BB + bb];
            }
        }
        g_z[(size_t)b * DINNER + d] = rn_tf32(y * gv);
    }
}

// ===================================================================
// Epilogue C: sum out_proj partials [z][m][b] -> out (B, DMODEL)
// grid (DMODEL/64, 4): blockIdx.y selects 8 batches
// ===================================================================
__global__ void __launch_bounds__(256) epi_c_kernel(float* __restrict__ out) {
    __shared__ float tile[64][9];
    int m0 = blockIdx.x * 64;
    int by = blockIdx.y;          // batches [8*by, 8*by+8)
    int tid = threadIdx.x;
    {
        int ml = tid >> 2;        // 0..63
        int bq = tid & 3;         // 0..3 (2 b's each)
        float2 s = make_float2(0.f, 0.f);
#pragma unroll
        for (int z = 0; z < SPLIT_OUT; z++) {
            const float2* p = (const float2*)(g_part_c +
                ((size_t)z * DMODEL + m0 + ml) * BATCH + by * 8 + bq * 2);
            float2 v = p[0];
            s.x += v.x; s.y += v.y;
        }
        tile[ml][bq * 2] = s.x;
        tile[ml][bq * 2 + 1] = s.y;
    }
    __syncthreads();
    {
        int b = tid >> 5;         // 0..7
        int mq = (tid & 31) * 2;  // 0..62
        float* dst = out + (size_t)(by * 8 + b) * DMODEL + m0 + mq;
        *(float2*)dst = make_float2(tile[mq][b], tile[mq + 1][b]);
    }
}

// ===================================================================
extern "C" void kernel_launch(void* const* d_in, const int* in_sizes, int n_in,
                              void* d_out, int out_size) {
    const float* x    = (const float*)d_in[0];
    const float* cs   = (const float*)d_in[1];
    const float* cw   = (const float*)d_in[2];
    const float* cb   = (const float*)d_in[3];
    const float* Wssm = (const float*)d_in[4];
    const float* Wmlp = (const float*)d_in[5];
    const float* Wout = (const float*)d_in[6];
    const float* Wxp  = (const float*)d_in[7];
    const float* Wdt  = (const float*)d_in[8];
    const float* dtb  = (const float*)d_in[9];
    const float* Alog = (const float*)d_in[10];
    const float* Dv   = (const float*)d_in[11];
    const float* sst  = (const float*)d_in[12];
    float* out = (float*)d_out;

    cudaFuncSetAttribute(gemm_in_kernel,
                         cudaFuncAttributeMaxDynamicSharedMemorySize, GEMM_SMEM);
    cudaFuncSetAttribute(gemm_xp_kernel,
                         cudaFuncAttributeMaxDynamicSharedMemorySize, GEMM_SMEM);
    cudaFuncSetAttribute(gemm_out_kernel,
                         cudaFuncAttributeMaxDynamicSharedMemorySize, GEMM_SMEM);

    prep_x_kernel<<<(BATCH * DMODEL + 255) / 256, 256>>>(x);
    gemm_in_kernel<<<dim3(DINNER / TROWS, 2, SPLIT_IN), 256, GEMM_SMEM>>>(Wssm, Wmlp);
    epi_a_kernel<<<dim3(DINNER / 128, 4), 128>>>(cs, cw, cb);
    gemm_xp_kernel<<<dim3(1, 1, SPLIT_XP), 256, GEMM_SMEM>>>(Wxp);
    epi_b1_kernel<<<192, 256>>>();
    ssm_kernel<<<dim3(DINNER / 128, 8), 128>>>(Wdt, dtb, Alog, Dv, sst);
    gemm_out_kernel<<<dim3(DMODEL / TROWS, 1, SPLIT_OUT), 256, GEMM_SMEM>>>(Wout);
    epi_c_kernel<<<dim3(DMODEL / 64, 4), 256>>>(out);
}

// round 14
// speedup vs baseline: 1.1406x; 1.1406x over previous
#include <cuda_runtime.h>
#include <cstdint>
#include <cstddef>

// Problem constants
#define BATCH   32
#define DMODEL  2560
#define DINNER  5120
#define NSTATE  16
#define DTRANK  160
#define XDBDIM  192          // DTRANK + 2*NSTATE

// Split-K configs (one-wave grids; GEMM = 1 block/SM due to smem)
#define SPLIT_IN   3         // K=2560 -> 864/864/832   (grid 20*2*3 = 120)
#define SPLIT_XP   80        // K=5120 -> 64 each       (grid 80)
#define SPLIT_OUT  14        // K=5120 -> 10x384+4x320  (grid 10*14 = 140)

#define KCH    32            // k per pipeline chunk
#define KPAD   36            // padded smem row stride (floats; 144B)
#define NSTAGE 4
#define TROWS  256
#define GEMM_SMEM (NSTAGE * (TROWS + 32) * KPAD * 4)   // 165888 bytes

// -------- scratch (static device globals; no allocation) ----------
__device__ __align__(256) float g_x32[BATCH * DMODEL];            // rna-tf32 x
__device__ __align__(256) float g_part_in[(2 * SPLIT_IN) * DINNER * BATCH];
__device__ __align__(256) float g_conv[BATCH * DINNER];           // rna-tf32
__device__ __align__(256) float g_g[BATCH * DINNER];
__device__ __align__(256) float g_part_b[SPLIT_XP * XDBDIM * BATCH];
__device__ __align__(256) float g_red[8 * XDBDIM * BATCH];
__device__ __align__(256) float g_xdbT[XDBDIM * BATCH];
__device__ __align__(256) float g_z[BATCH * DINNER];              // rna-tf32
__device__ __align__(256) float g_part_c[SPLIT_OUT * DMODEL * BATCH];

// -------- helpers ----------
__device__ __forceinline__ uint32_t smem_u32(const void* p) {
    uint32_t r;
    asm("{.reg .u64 t; cvta.to.shared.u64 t, %1; cvt.u32.u64 %0, t;}"
        : "=r"(r) : "l"(p));
    return r;
}
__device__ __forceinline__ void cp_async16(uint32_t dst, const void* src) {
    asm volatile("cp.async.cg.shared.global [%0], [%1], 16;\n" ::"r"(dst), "l"(src));
}
__device__ __forceinline__ void cp_commit() {
    asm volatile("cp.async.commit_group;\n");
}
template <int N>
__device__ __forceinline__ void cp_wait() {
    asm volatile("cp.async.wait_group %0;\n" ::"n"(N));
}
__device__ __forceinline__ float silu_f(float v) {
    return v / (1.f + __expf(-v));
}
__device__ __forceinline__ float rn_tf32(float v) {
    uint32_t u;
    asm("cvt.rna.tf32.f32 %0, %1;" : "=r"(u) : "f"(v));
    return __uint_as_float(u);
}
__device__ __forceinline__ uint32_t rn_tf32_r(uint32_t v) {
    uint32_t u;
    asm("cvt.rna.tf32.f32 %0, %1;" : "=r"(u) : "f"(__uint_as_float(v)));
    return u;
}

// ldmatrix x4: four 8x8 b16 matrices (= four 8x4 fp32 blocks)
__device__ __forceinline__ void ldsm_x4(uint32_t& r0, uint32_t& r1,
                                        uint32_t& r2, uint32_t& r3,
                                        uint32_t addr) {
    asm volatile("ldmatrix.sync.aligned.m8n8.x4.shared.b16 {%0,%1,%2,%3}, [%4];"
                 : "=r"(r0), "=r"(r1), "=r"(r2), "=r"(r3) : "r"(addr));
}

// warp mma: D(16x8) += A(16x8,row) * B(8x8,col), tf32 inputs, f32 accum
__device__ __forceinline__ void mma_tf32(float* c, const uint32_t* a,
                                         const uint32_t* b) {
    asm volatile(
        "mma.sync.aligned.m16n8k8.row.col.f32.tf32.tf32.f32 "
        "{%0,%1,%2,%3}, {%4,%5,%6,%7}, {%8,%9}, {%0,%1,%2,%3};"
        : "+f"(c[0]), "+f"(c[1]), "+f"(c[2]), "+f"(c[3])
        : "r"(a[0]), "r"(a[1]), "r"(a[2]), "r"(a[3]), "r"(b[0]), "r"(b[1]));
}

// ===================================================================
// prep: round x to tf32-nearest (B operand of in-proj)
// ===================================================================
__global__ void __launch_bounds__(256) prep_x_kernel(const float* __restrict__ x) {
    int i = blockIdx.x * 256 + threadIdx.x;
    if (i < BATCH * DMODEL) g_x32[i] = rn_tf32(x[i]);
}

// ===================================================================
// Warp-MMA tf32 split-K GEMM: 256 threads, tile = 256 rows x 32 batch.
// Fragments via ldmatrix.x4.  4-stage cp.async pipeline, ONE
// __syncthreads per chunk.  A RNA-rounded post-ldmatrix; B pre-rounded.
// Writes partial to part[d*32 + b].  klen multiple of KCH.
// ===================================================================
__device__ __forceinline__ void gemm_mma(const float* __restrict__ W,
                                         const float* __restrict__ Bm,
                                         float* __restrict__ part,
                                         int M, int K, int k0, int klen, int row0) {
    extern __shared__ __align__(16) float dyn[];
    float* w_s = dyn;                             // [NSTAGE][TROWS*KPAD]
    float* x_s = dyn + NSTAGE * TROWS * KPAD;     // [NSTAGE][32*KPAD]

    const int tid = threadIdx.x;
    const int wid = tid >> 5;
    const int lane = tid & 31;
    const int gid = lane >> 2;    // 0..7
    const int t4 = lane & 3;      // 0..3
    const int lm = lane >> 3;     // ldmatrix matrix idx 0..3
    const int lr = lane & 7;      // ldmatrix row in matrix

    const int nch = klen / KCH;

    uint32_t ws_[NSTAGE], xs_[NSTAGE];
#pragma unroll
    for (int s = 0; s < NSTAGE; s++) {
        ws_[s] = smem_u32(w_s + s * TROWS * KPAD);
        xs_[s] = smem_u32(x_s + s * 32 * KPAD);
    }

    uint32_t a_off[2];
#pragma unroll
    for (int mt = 0; mt < 2; mt++)
        a_off[mt] = (uint32_t)(((wid * 32 + mt * 16 + (lm & 1) * 8 + lr) * KPAD
                                + (lm >> 1) * 4) * 4);
    uint32_t b_off[2];
#pragma unroll
    for (int p = 0; p < 2; p++)
        b_off[p] = (uint32_t)((((lm >> 1) * 8 + p * 16 + lr) * KPAD
                               + (lm & 1) * 4) * 4);

    auto fill = [&](int st, int c) {
        const int kc = k0 + c * KCH;
        uint32_t wd = ws_[st];
#pragma unroll
        for (int i = 0; i < 8; i++) {
            int p = tid + 256 * i;             // 0..2047
            int r = p >> 3, o = p & 7;
            int gr = row0 + r;
            gr = gr < M ? gr : M - 1;          // clamp (xp tail rows)
            cp_async16(wd + (uint32_t)(r * KPAD + o * 4) * 4,
                       W + (size_t)gr * K + kc + o * 4);
        }
        {
            int r = tid >> 3, o = tid & 7;     // 256 pieces exactly
            cp_async16(xs_[st] + (uint32_t)(r * KPAD + o * 4) * 4,
                       Bm + (size_t)r * K + kc + o * 4);
        }
        cp_commit();
    };

    fill(0, 0);
#pragma unroll
    for (int s = 1; s <= NSTAGE - 2; s++) {
        if (s < nch) fill(s % NSTAGE, s); else cp_commit();
    }

    float acc[2][4][4];
#pragma unroll
    for (int mt = 0; mt < 2; mt++)
#pragma unroll
        for (int nt = 0; nt < 4; nt++)
#pragma unroll
            for (int q = 0; q < 4; q++) acc[mt][nt][q] = 0.f;

    for (int c = 0; c < nch; c++) {
        cp_wait<NSTAGE - 2>();
        __syncthreads();
        const int st = c % NSTAGE;
        const uint32_t wsb = ws_[st];
        const uint32_t xsb = xs_[st];
#pragma unroll
        for (int kstep = 0; kstep < KCH / 8; kstep++) {
            const uint32_t kb = kstep * 32;   // 8 floats = 32 bytes
            uint32_t a[2][4], b[4][2];
#pragma unroll
            for (int mt = 0; mt < 2; mt++) {
                ldsm_x4(a[mt][0], a[mt][1], a[mt][2], a[mt][3],
                        wsb + a_off[mt] + kb);
                a[mt][0] = rn_tf32_r(a[mt][0]);
                a[mt][1] = rn_tf32_r(a[mt][1]);
                a[mt][2] = rn_tf32_r(a[mt][2]);
                a[mt][3] = rn_tf32_r(a[mt][3]);
            }
#pragma unroll
            for (int p = 0; p < 2; p++)
                ldsm_x4(b[p * 2][0], b[p * 2][1], b[p * 2 + 1][0],
                        b[p * 2 + 1][1], xsb + b_off[p] + kb);
#pragma unroll
            for (int mt = 0; mt < 2; mt++)
#pragma unroll
                for (int nt = 0; nt < 4; nt++)
                    mma_tf32(acc[mt][nt], a[mt], b[nt]);
        }
        if (c + NSTAGE - 1 < nch) fill((c + NSTAGE - 1) % NSTAGE, c + NSTAGE - 1);
        else cp_commit();
    }

    // store: D[m][n] -> part[d*32 + b]
#pragma unroll
    for (int mt = 0; mt < 2; mt++) {
        int d0 = row0 + wid * 32 + mt * 16 + gid;
        if (d0 < M) {
#pragma unroll
            for (int nt = 0; nt < 4; nt++) {
                int n = nt * 8 + 2 * t4;
                *(float2*)&part[(size_t)d0 * BATCH + n] =
                    make_float2(acc[mt][nt][0], acc[mt][nt][1]);
                if (d0 + 8 < M)
                    *(float2*)&part[(size_t)(d0 + 8) * BATCH + n] =
                        make_float2(acc[mt][nt][2], acc[mt][nt][3]);
            }
        }
    }
}

// ---- wrappers ----
__global__ void __launch_bounds__(256)
gemm_in_kernel(const float* __restrict__ Wssm, const float* __restrict__ Wmlp) {
    int sel = blockIdx.y, z = blockIdx.z;
    const float* W = sel ? Wmlp : Wssm;
    int k0 = z * 864;
    int klen = (z < 2) ? 864 : 832;
    float* part = g_part_in + (size_t)(sel * SPLIT_IN + z) * DINNER * BATCH;
    gemm_mma(W, g_x32, part, DINNER, DMODEL, k0, klen, blockIdx.x * TROWS);
}

__global__ void __launch_bounds__(256)
gemm_xp_kernel(const float* __restrict__ Wxp) {
    int z = blockIdx.z;
    float* part = g_part_b + (size_t)z * XDBDIM * BATCH;
    gemm_mma(Wxp, g_conv, part, XDBDIM, DINNER, z * (DINNER / SPLIT_XP),
             DINNER / SPLIT_XP, 0);
}

__global__ void __launch_bounds__(256)
gemm_out_kernel(const float* __restrict__ Wout) {
    int z = blockIdx.z;
    int k0 = z < 10 ? z * 384 : 3840 + (z - 10) * 320;
    int klen = z < 10 ? 384 : 320;
    float* part = g_part_c + (size_t)z * DMODEL * BATCH;
    gemm_mma(Wout, g_z, part, DMODEL, DINNER, k0, klen, blockIdx.x * TROWS);
}

// ===================================================================
// Epilogue A: sum in_proj partials [z][d][b], conv + SiLU -> g_conv[b][d]
//             (tf32-rounded), gate SiLU -> g_g[b][d]
// grid (DINNER/128, 4): blockIdx.y selects 8 batches
// ===================================================================
__global__ void __launch_bounds__(128)
epi_a_kernel(const float* __restrict__ conv_states,
             const float* __restrict__ conv_w,
             const float* __restrict__ conv_b) {
    int d = blockIdx.x * 128 + threadIdx.x;
    int by = blockIdx.y;          // 0..3, batches [8*by, 8*by+8)
    float xs[8], res[8];
#pragma unroll
    for (int b = 0; b < 8; b++) { xs[b] = 0.f; res[b] = 0.f; }
#pragma unroll
    for (int z = 0; z < SPLIT_IN; z++) {
        const float4* p = (const float4*)(g_part_in +
            ((size_t)z * DINNER + d) * BATCH + by * 8);
        float4 v0 = p[0], v1 = p[1];
        xs[0] += v0.x; xs[1] += v0.y; xs[2] += v0.z; xs[3] += v0.w;
        xs[4] += v1.x; xs[5] += v1.y; xs[6] += v1.z; xs[7] += v1.w;
    }
#pragma unroll
    for (int z = SPLIT_IN; z < 2 * SPLIT_IN; z++) {
        const float4* p = (const float4*)(g_part_in +
            ((size_t)z * DINNER + d) * BATCH + by * 8);
        float4 v0 = p[0], v1 = p[1];
        res[0] += v0.x; res[1] += v0.y; res[2] += v0.z; res[3] += v0.w;
        res[4] += v1.x; res[5] += v1.y; res[6] += v1.z; res[7] += v1.w;
    }

    float cw0 = conv_w[d];
    float cw1 = conv_w[DINNER + d];
    float cw2 = conv_w[2 * DINNER + d];
    float cw3 = conv_w[3 * DINNER + d];
    float cb = conv_b[d];

#pragma unroll
    for (int bb = 0; bb < 8; bb++) {
        int b = by * 8 + bb;
        float conv = conv_states[(size_t)(1 * BATCH + b) * DINNER + d] * cw0
                   + conv_states[(size_t)(2 * BATCH + b) * DINNER + d] * cw1
                   + conv_states[(size_t)(3 * BATCH + b) * DINNER + d] * cw2
                   + xs[bb] * cw3 + cb;
        g_conv[(size_t)b * DINNER + d] = rn_tf32(silu_f(conv));
        g_g[(size_t)b * DINNER + d] = silu_f(res[bb]);
    }
}

// ===================================================================
// Epilogue B: two-stage reduction of x_proj partials [z][t]
// ===================================================================
__global__ void __launch_bounds__(256) epi_b1_kernel() {
    int g = blockIdx.x / 24;
    int t = (blockIdx.x % 24) * 256 + threadIdx.x;
    const float* base = g_part_b + (size_t)(g * 10) * XDBDIM * BATCH + t;
    float s = 0.f;
#pragma unroll
    for (int j = 0; j < 10; j++)
        s += base[(size_t)j * XDBDIM * BATCH];
    g_red[(size_t)g * XDBDIM * BATCH + t] = s;
}

__global__ void __launch_bounds__(256) epi_b2_kernel() {
    int t = blockIdx.x * 256 + threadIdx.x;
    float s = 0.f;
#pragma unroll
    for (int g = 0; g < 8; g++)
        s += g_red[(size_t)g * XDBDIM * BATCH + t];
    g_xdbT[t] = s;
}

// ===================================================================
// SSM kernel: dt GEMV + softplus + state scan + gate -> g_z[b][d] (tf32)
// grid (DINNER/128, 8), block 128; blockIdx.y = 4-batch group
// ===================================================================
#define SSM_BB 4
__global__ void __launch_bounds__(128)
ssm_kernel(const float* __restrict__ W_dt, const float* __restrict__ dt_bias,
           const float* __restrict__ A_log, const float* __restrict__ Dv,
           const float* __restrict__ ssm_state) {
    __shared__ float xdb_s[XDBDIM * SSM_BB];
    const int by = blockIdx.y;
    for (int u = threadIdx.x; u < XDBDIM * SSM_BB; u += 128) {
        int r = u >> 2, bb = u & 3;
        xdb_s[u] = g_xdbT[(size_t)r * BATCH + by * SSM_BB + bb];
    }
    __syncthreads();

    const int d = blockIdx.x * 128 + threadIdx.x;

    float accdt[SSM_BB];
#pragma unroll
    for (int bb = 0; bb < SSM_BB; bb++) accdt[bb] = 0.f;

    const float4* wd = (const float4*)(W_dt + (size_t)d * DTRANK);
#pragma unroll 10
    for (int r4 = 0; r4 < DTRANK / 4; r4++) {
        float4 w = wd[r4];
        float wa[4] = {w.x, w.y, w.z, w.w};
#pragma unroll
        for (int j = 0; j < 4; j++) {
            float4 xv = *(const float4*)&xdb_s[(r4 * 4 + j) * SSM_BB];
            accdt[0] += wa[j] * xv.x;
            accdt[1] += wa[j] * xv.y;
            accdt[2] += wa[j] * xv.z;
            accdt[3] += wa[j] * xv.w;
        }
    }

    float a[NSTATE];
    const float4* al = (const float4*)(A_log + (size_t)d * NSTATE);
#pragma unroll
    for (int n4 = 0; n4 < 4; n4++) {
        float4 v = al[n4];
        a[n4 * 4 + 0] = -__expf(v.x);
        a[n4 * 4 + 1] = -__expf(v.y);
        a[n4 * 4 + 2] = -__expf(v.z);
        a[n4 * 4 + 3] = -__expf(v.w);
    }
    float Dd = Dv[d];
    float bias = dt_bias[d];

#pragma unroll
    for (int bb = 0; bb < SSM_BB; bb++) {
        int b = by * SSM_BB + bb;
        float dtv = accdt[bb] + bias;
        float dt = dtv > 20.f ? dtv : log1pf(__expf(dtv));
        float c = g_conv[(size_t)b * DINNER + d];
        float gv = g_g[(size_t)b * DINNER + d];
        float y = Dd * c;
        const float4* s4 =
            (const float4*)(ssm_state + ((size_t)b * DINNER + d) * NSTATE);
#pragma unroll
        for (int n4 = 0; n4 < 4; n4++) {
            float4 s = s4[n4];
            float sa[4] = {s.x, s.y, s.z, s.w};
#pragma unroll
            for (int h = 0; h < 4; h++) {
                int n = n4 * 4 + h;
                float dA = __expf(dt * a[n]);
                float hv = sa[h] * dA + dt * xdb_s[(DTRANK + n) * SSM_BB + bb] * c;
                y += hv * xdb_s[(DTRANK + NSTATE + n) * SSM_BB + bb];
            }
        }
        g_z[(size_t)b * DINNER + d] = rn_tf32(y * gv);
    }
}

// ===================================================================
// Epilogue C: sum out_proj partials [z][m][b] -> out (B, DMODEL)
// grid (DMODEL/64, 4): blockIdx.y selects 8 batches
// ===================================================================
__global__ void __launch_bounds__(256) epi_c_kernel(float* __restrict__ out) {
    __shared__ float tile[64][9];
    int m0 = blockIdx.x * 64;
    int by = blockIdx.y;          // batches [8*by, 8*by+8)
    int tid = threadIdx.x;
    {
        int ml = tid >> 2;        // 0..63
        int bq = tid & 3;         // 0..3 (2 b's each)
        float2 s = make_float2(0.f, 0.f);
#pragma unroll
        for (int z = 0; z < SPLIT_OUT; z++) {
            const float2* p = (const float2*)(g_part_c +
                ((size_t)z * DMODEL + m0 + ml) * BATCH + by * 8 + bq * 2);
            float2 v = p[0];
            s.x += v.x; s.y += v.y;
        }
        tile[ml][bq * 2] = s.x;
        tile[ml][bq * 2 + 1] = s.y;
    }
    __syncthreads();
    {
        int b = tid >> 5;         // 0..7
        int mq = (tid & 31) * 2;  // 0..62
        float* dst = out + (size_t)(by * 8 + b) * DMODEL + m0 + mq;
        *(float2*)dst = make_float2(tile[mq][b], tile[mq + 1][b]);
    }
}

// ===================================================================
extern "C" void kernel_launch(void* const* d_in, const int* in_sizes, int n_in,
                              void* d_out, int out_size) {
    const float* x    = (const float*)d_in[0];
    const float* cs   = (const float*)d_in[1];
    const float* cw   = (const float*)d_in[2];
    const float* cb   = (const float*)d_in[3];
    const float* Wssm = (const float*)d_in[4];
    const float* Wmlp = (const float*)d_in[5];
    const float* Wout = (const float*)d_in[6];
    const float* Wxp  = (const float*)d_in[7];
    const float* Wdt  = (const float*)d_in[8];
    const float* dtb  = (const float*)d_in[9];
    const float* Alog = (const float*)d_in[10];
    const float* Dv   = (const float*)d_in[11];
    const float* sst  = (const float*)d_in[12];
    float* out = (float*)d_out;

    cudaFuncSetAttribute(gemm_in_kernel,
                         cudaFuncAttributeMaxDynamicSharedMemorySize, GEMM_SMEM);
    cudaFuncSetAttribute(gemm_xp_kernel,
                         cudaFuncAttributeMaxDynamicSharedMemorySize, GEMM_SMEM);
    cudaFuncSetAttribute(gemm_out_kernel,
                         cudaFuncAttributeMaxDynamicSharedMemorySize, GEMM_SMEM);

    prep_x_kernel<<<(BATCH * DMODEL + 255) / 256, 256>>>(x);
    gemm_in_kernel<<<dim3(DINNER / TROWS, 2, SPLIT_IN), 256, GEMM_SMEM>>>(Wssm, Wmlp);
    epi_a_kernel<<<dim3(DINNER / 128, 4), 128>>>(cs, cw, cb);
    gemm_xp_kernel<<<dim3(1, 1, SPLIT_XP), 256, GEMM_SMEM>>>(Wxp);
    epi_b1_kernel<<<192, 256>>>();
    epi_b2_kernel<<<24, 256>>>();
    ssm_kernel<<<dim3(DINNER / 128, 8), 128>>>(Wdt, dtb, Alog, Dv, sst);
    gemm_out_kernel<<<dim3(DMODEL / TROWS, 1, SPLIT_OUT), 256, GEMM_SMEM>>>(Wout);
    epi_c_kernel<<<dim3(DMODEL / 64, 4), 256>>>(out);
}